// round 11
// baseline (speedup 1.0000x reference)
#include <cuda_runtime.h>
#include <cuda_bf16.h>
#include <math.h>

#define NQ 256
#define MM 256
#define EE 128
#define HH 4
#define PP 64
#define NK (NQ*MM)        // 65536 keys
#define CHUNK 128
#define NCH (NK/CHUNK)    // 512 chunks per head

// ---------------- device scratch (static: no allocation allowed) ----------
__device__ float gPxT[NQ*EE];
__device__ float gPyT[MM*EE];
__device__ float gGxT[NQ*EE];
__device__ float gGyT[MM*EE];
__device__ float gQxT[NQ*EE];             // theta_x @ x^T
__device__ float gdphi[EE];
__device__ float gdg[EE];
__device__ float gdth[EE];
__device__ float gCthT[PP*EE];            // f32 [p][e]  (theta_e @ q_w2)^T
__device__ float gQ[HH*NQ*32];            // pre-scaled by 1/sqrt(32)*log2(e)
__device__ unsigned short gCphiB[EE*PP];  // bf16 [e][p]
__device__ unsigned short gCgB[EE*PP];    // bf16 [e][p]
__device__ unsigned short gPartOB[(size_t)HH*NQ*NCH*32];  // bf16, 33.5 MB
__device__ float gPartL[HH*NQ*NCH];       // 2 MB
__device__ float gAccO[HH*NQ*32];         // 128 KB
__device__ float gAccL[HH*NQ];

// ---------------- mma / ldmatrix helpers ------------------------------------
__device__ __forceinline__ unsigned pk(float lo, float hi) {
    unsigned d;
    asm("cvt.rn.bf16x2.f32 %0, %1, %2;" : "=r"(d) : "f"(hi), "f"(lo));
    return d;
}
__device__ __forceinline__ float ex2(float x) {
    float d;
    asm("ex2.approx.f32 %0, %1;" : "=f"(d) : "f"(x));
    return d;
}
__device__ __forceinline__ void mma16816(float* c, const unsigned* a, const unsigned* b) {
    asm volatile(
        "mma.sync.aligned.m16n8k16.row.col.f32.bf16.bf16.f32 "
        "{%0,%1,%2,%3},{%4,%5,%6,%7},{%8,%9},{%0,%1,%2,%3};"
        : "+f"(c[0]), "+f"(c[1]), "+f"(c[2]), "+f"(c[3])
        : "r"(a[0]), "r"(a[1]), "r"(a[2]), "r"(a[3]), "r"(b[0]), "r"(b[1]));
}
__device__ __forceinline__ void ldsm4(unsigned& x, unsigned& y, unsigned& z, unsigned& w,
                                      unsigned addr) {
    asm volatile("ldmatrix.sync.aligned.m8n8.x4.shared.b16 {%0,%1,%2,%3}, [%4];"
                 : "=r"(x), "=r"(y), "=r"(z), "=r"(w) : "r"(addr));
}
__device__ __forceinline__ void ldsm4t(unsigned& x, unsigned& y, unsigned& z, unsigned& w,
                                       unsigned addr) {
    asm volatile("ldmatrix.sync.aligned.m8n8.x4.trans.shared.b16 {%0,%1,%2,%3}, [%4];"
                 : "=r"(x), "=r"(y), "=r"(z), "=r"(w) : "r"(addr));
}

// ---------------- 1: proj (bf16 mma) + cd, one launch -----------------------
#define PJ_W_OFF 0
#define PJ_R_OFF 69632
#define WE_PITCH 129
#define PC_SMEM  98816
__global__ void __launch_bounds__(256) projcd_kernel(
        const float* __restrict__ x, const float* __restrict__ y,
        const float* __restrict__ phi_w, const float* __restrict__ g_w,
        const float* __restrict__ theta_w,
        const float* __restrict__ k_w2, const float* __restrict__ k_b2,
        const float* __restrict__ q_w2, const float* __restrict__ q_b2) {
    extern __shared__ char smc[];
    int tid = threadIdx.x;  // 256
    if (blockIdx.x < 40) {
        unsigned short* Wb = (unsigned short*)(smc + PJ_W_OFF);  // [128][264]
        unsigned short* Rb = (unsigned short*)(smc + PJ_R_OFF);  // [32][264]
        int combo = blockIdx.x >> 3;   // 0..4
        int rt    = blockIdx.x & 7;    // 32-row tile
        const float* w    = (combo < 2) ? phi_w : (combo < 4) ? g_w : theta_w;
        const float* srcp = (combo == 1 || combo == 3) ? y : x;
        float* outT = combo==0 ? gPxT : combo==1 ? gPyT : combo==2 ? gGxT
                    : combo==3 ? gGyT : gQxT;
        for (int idx = tid; idx < 128*128; idx += 256) {
            int e = idx >> 7, c = idx & 127;
            float2 f = *(const float2*)(w + e*384 + c*2);
            ((unsigned*)(Wb + e*264))[c] = pk(f.x, f.y);
        }
        for (int idx = tid; idx < 32*128; idx += 256) {
            int r = idx >> 7, c = idx & 127;
            float2 f = *(const float2*)(srcp + (rt*32 + r)*256 + c*2);
            ((unsigned*)(Rb + r*264))[c] = pk(f.x, f.y);
        }
        __syncthreads();
        int wq = tid >> 5, lane = tid & 31, g = lane >> 2, q = lane & 3;
        int mtile = wq & 1;
        int eg    = wq >> 1;
        int arow = mtile*16 + (lane & 7) + ((lane >> 3) & 1)*8;
        int acol = ((lane >> 4) & 1)*8;
        unsigned rbase = (unsigned)__cvta_generic_to_shared(Rb);
        unsigned wbase = (unsigned)__cvta_generic_to_shared(Wb)
                       + (unsigned)(((eg*32 + (lane & 7))*264 + (lane >> 3)*8)*2);
        float C[4][4];
        #pragma unroll
        for (int ng = 0; ng < 4; ++ng)
            #pragma unroll
            for (int i = 0; i < 4; ++i) C[ng][i] = 0.f;
        #pragma unroll
        for (int kb = 0; kb < 8; ++kb) {
            unsigned A0[4], A1[4];
            unsigned abase = rbase + (unsigned)((arow*264 + kb*32 + acol)*2);
            ldsm4(A0[0], A0[1], A0[2], A0[3], abase);
            ldsm4(A1[0], A1[1], A1[2], A1[3], abase + 32);
            #pragma unroll
            for (int ng = 0; ng < 4; ++ng) {
                unsigned b[4];
                ldsm4(b[0], b[1], b[2], b[3], wbase + (unsigned)((ng*8*264 + kb*32)*2));
                mma16816(C[ng], A0, b);
                mma16816(C[ng], A1, b + 2);
            }
        }
        int row = rt*32 + mtile*16 + g;
        #pragma unroll
        for (int ng = 0; ng < 4; ++ng) {
            int e = eg*32 + ng*8 + 2*q;
            float2 v0; v0.x = C[ng][0]; v0.y = C[ng][1];
            float2 v1; v1.x = C[ng][2]; v1.y = C[ng][3];
            *(float2*)(outT + row*128 + e)     = v0;
            *(float2*)(outT + (row+8)*128 + e) = v1;
        }
    } else {
        float* we  = (float*)smc;              // 128 x 129
        float* kw2 = (float*)(smc + 66048);    // 128 x 64
        int bid2 = blockIdx.x - 40;
        int wi = bid2 % 3;
        int pg = bid2 / 3;
        const float* w   = wi==0 ? phi_w : wi==1 ? g_w : theta_w;
        const float* w2  = wi==2 ? q_w2 : k_w2;
        const float* b2  = wi==2 ? q_b2 : k_b2;
        unsigned short* CtB = wi==1 ? gCgB : gCphiB;
        float* dv  = wi==0 ? gdphi : wi==1 ? gdg : gdth;
        for (int idx = tid; idx < 128*128; idx += 256) {
            int e = idx >> 7, c = idx & 127;
            we[e*WE_PITCH + c] = w[e*384 + 256 + c];
        }
        for (int idx = tid; idx < 128*64; idx += 256) kw2[idx] = w2[idx];
        __syncthreads();
        int e  = tid & 127;
        int ph = tid >> 7;
        if (pg == 0 && ph == 0) {
            float acc = 0.f;
            for (int c = 0; c < 128; ++c) acc += we[e*WE_PITCH + c]*b2[c];
            dv[e] = acc;
        }
        for (int j = 0; j < 4; ++j) {
            int p = pg*8 + ph*4 + j;
            float acc = 0.f;
            #pragma unroll 8
            for (int c = 0; c < 128; ++c)
                acc += we[e*WE_PITCH + c] * kw2[c*64 + p];
            if (wi == 2) {
                gCthT[p*128 + e] = acc;
            } else {
                __nv_bfloat16 b = __float2bfloat16(acc);
                CtB[e*64 + p] = *(unsigned short*)&b;
            }
        }
    }
}

// ---------------- 3: Q = scale * (Qx + Cth^T hid + dth) ---------------------
__global__ void q_kernel(const float* __restrict__ x_pos,
                         const float* __restrict__ q_w1,
                         const float* __restrict__ q_b1) {
    __shared__ float hid[64];
    int n = blockIdx.x;
    int t = threadIdx.x;   // 128
    if (t < 64) {
        float r0 = x_pos[n*3], r1 = x_pos[n*3+1], r2 = x_pos[n*3+2];
        float h = q_w1[t*3]*r0 + q_w1[t*3+1]*r1 + q_w1[t*3+2]*r2 + q_b1[t];
        hid[t] = fmaxf(h, 0.f);
    }
    __syncthreads();
    int e = t;
    float a0 = 0.f, a1 = 0.f;
    #pragma unroll
    for (int p = 0; p < 64; p += 2) {
        a0 += gCthT[p*128 + e]     * hid[p];
        a1 += gCthT[(p+1)*128 + e] * hid[p+1];
    }
    float acc = gQxT[n*128 + e] + a0 + a1 + gdth[e];
    acc *= 0.17677669529663687f * 1.4426950408889634f;
    int h = e >> 5, d = e & 31;
    gQ[(h*NQ + n)*32 + d] = acc;
}

// ---------------- 4: FUSED genkv + flash attention (128-key half blocks) ----
#define KPITCH 136
#define FZ_KS_OFF 0
#define FZ_VS_OFF 34816
#define FZ_BK_OFF 69632
#define FZ_BV_OFF 70144
#define FZ_YP_OFF 70656
#define FZ_SMEM   72192

__global__ void __launch_bounds__(256, 2) fused_kernel(
        const float* __restrict__ x_pos, const float* __restrict__ y_pos,
        const float* __restrict__ k_w1, const float* __restrict__ k_b1) {
    extern __shared__ char smc[];
    unsigned short* Ks = (unsigned short*)(smc + FZ_KS_OFF);  // [128][136] bf16
    unsigned short* Vs = (unsigned short*)(smc + FZ_VS_OFF);  // [128][136] bf16
    float* baseK = (float*)(smc + FZ_BK_OFF);
    float* baseV = (float*)(smc + FZ_BV_OFF);
    float* yps   = (float*)(smc + FZ_YP_OFF);                 // [128][3]
    __shared__ float kw1s[192], kb1s[64];
    int tid = threadIdx.x;          // 256
    int np = blockIdx.x >> 1;       // 0..255
    int mh = blockIdx.x & 1;        // key half
    int ch = blockIdx.x;            // chunk index (NCH=512)

    // ---- phase A: stage constants ----
    if (tid < 128) {
        baseK[tid] = gPxT[np*128 + tid] + gdphi[tid];
        baseV[tid] = gGxT[np*128 + tid] + gdg[tid];
    }
    for (int i = tid; i < 384; i += 256) yps[i] = y_pos[mh*384 + i];
    if (tid < 192) kw1s[tid] = k_w1[tid];
    if (tid < 64)  kb1s[tid] = k_b1[tid];
    __syncthreads();

    int w = tid >> 5, lane = tid & 31, g = lane >> 2, q = lane & 3;
    float xp0 = x_pos[np*3], xp1 = x_pos[np*3+1], xp2 = x_pos[np*3+2];

    // ---- phase B: K/V = H@C + base - Py/Gy -> SMEM (8 warps x 16 rows) ----
    {
        int rA = w*16 + g, rB = rA + 8;
        float ra0 = xp0 - yps[rA*3], ra1 = xp1 - yps[rA*3+1], ra2 = xp2 - yps[rA*3+2];
        float rb0 = xp0 - yps[rB*3], rb1 = xp1 - yps[rB*3+1], rb2 = xp2 - yps[rB*3+2];
        unsigned A[4][4];
        #pragma unroll
        for (int kt = 0; kt < 4; ++kt) {
            int p0 = kt*16 + 2*q;
            float hA0, hA1, hB0, hB1;
            #define HV(p, r0_, r1_, r2_) \
                fmaxf(kw1s[(p)*3]*r0_ + kw1s[(p)*3+1]*r1_ + kw1s[(p)*3+2]*r2_ + kb1s[p], 0.f)
            hA0 = HV(p0,   ra0, ra1, ra2); hA1 = HV(p0+1, ra0, ra1, ra2);
            hB0 = HV(p0,   rb0, rb1, rb2); hB1 = HV(p0+1, rb0, rb1, rb2);
            A[kt][0] = pk(hA0, hA1);
            A[kt][1] = pk(hB0, hB1);
            hA0 = HV(p0+8, ra0, ra1, ra2); hA1 = HV(p0+9, ra0, ra1, ra2);
            hB0 = HV(p0+8, rb0, rb1, rb2); hB1 = HV(p0+9, rb0, rb1, rb2);
            A[kt][2] = pk(hA0, hA1);
            A[kt][3] = pk(hB0, hB1);
            #undef HV
        }
        int gm  = mh*128 + rA;
        int gm2 = mh*128 + rB;
        const unsigned short* cpr = gCphiB + g*64 + 2*q;
        const unsigned short* cgr = gCgB   + g*64 + 2*q;
        #pragma unroll 4
        for (int nt = 0; nt < 16; ++nt) {
            const unsigned short* cp = cpr + nt*8*64;
            const unsigned short* cg = cgr + nt*8*64;
            unsigned bP[4][2], bG[4][2];
            #pragma unroll
            for (int kt = 0; kt < 4; ++kt) {
                bP[kt][0] = *(const unsigned*)(cp + kt*16);
                bP[kt][1] = *(const unsigned*)(cp + kt*16 + 8);
                bG[kt][0] = *(const unsigned*)(cg + kt*16);
                bG[kt][1] = *(const unsigned*)(cg + kt*16 + 8);
            }
            float cK[4] = {0.f,0.f,0.f,0.f}, cV[4] = {0.f,0.f,0.f,0.f};
            #pragma unroll
            for (int kt = 0; kt < 4; ++kt) {
                mma16816(cK, A[kt], bP[kt]);
                mma16816(cV, A[kt], bG[kt]);
            }
            int e0 = nt*8 + 2*q;
            float2 pK0 = *(const float2*)(gPyT + gm*128  + e0);
            float2 pK1 = *(const float2*)(gPyT + gm2*128 + e0);
            float2 pV0 = *(const float2*)(gGyT + gm*128  + e0);
            float2 pV1 = *(const float2*)(gGyT + gm2*128 + e0);
            float2 bk = *(const float2*)(baseK + e0);
            float2 bv = *(const float2*)(baseV + e0);
            *(unsigned*)(Ks + rA*KPITCH + e0) = pk(cK[0]+bk.x-pK0.x, cK[1]+bk.y-pK0.y);
            *(unsigned*)(Ks + rB*KPITCH + e0) = pk(cK[2]+bk.x-pK1.x, cK[3]+bk.y-pK1.y);
            *(unsigned*)(Vs + rA*KPITCH + e0) = pk(cV[0]+bv.x-pV0.x, cV[1]+bv.y-pV0.y);
            *(unsigned*)(Vs + rB*KPITCH + e0) = pk(cV[2]+bv.x-pV1.x, cV[3]+bv.y-pV1.y);
        }
    }
    __syncthreads();

    // ---- phase C: 2 passes x (1 head, 4 q-tiles = 64 queries) per warp ----
    unsigned ksb = (unsigned)__cvta_generic_to_shared(Ks);
    unsigned vsb = (unsigned)__cvta_generic_to_shared(Vs);
    int kRow = (lane & 7) + ((lane >> 4) & 1)*8;
    int kCol = ((lane >> 3) & 1)*8;
    int vRow = (lane & 7) + ((lane >> 3) & 1)*8;
    int vCol = ((lane >> 4) & 1)*8;
    int hh  = w & 3;                       // head for this warp
    unsigned ak0 = ksb + (unsigned)((kRow*KPITCH + hh*32 + kCol)*2);
    unsigned av0 = vsb + (unsigned)((vRow*KPITCH + hh*32 + vCol)*2);
    const float* Qp = gQ + hh*NQ*32;
    for (int pass = 0; pass < 2; ++pass) {
        int qtg = (w >> 2) + 2*pass;       // 0..3
        int qb0 = qtg*64;                  // 64-query group base
        unsigned Aq[4][2][4];
        #pragma unroll
        for (int qt = 0; qt < 4; ++qt) {
            int rqA = qb0 + qt*16 + g, rqB = rqA + 8;
            #pragma unroll
            for (int kt = 0; kt < 2; ++kt) {
                int c0 = kt*16 + 2*q;
                float2 f;
                f = *(const float2*)(Qp + rqA*32 + c0);     Aq[qt][kt][0] = pk(f.x, f.y);
                f = *(const float2*)(Qp + rqB*32 + c0);     Aq[qt][kt][1] = pk(f.x, f.y);
                f = *(const float2*)(Qp + rqA*32 + c0 + 8); Aq[qt][kt][2] = pk(f.x, f.y);
                f = *(const float2*)(Qp + rqB*32 + c0 + 8); Aq[qt][kt][3] = pk(f.x, f.y);
            }
        }
        float O[4][4][4];
        float ls[4][2];
        #pragma unroll
        for (int qt = 0; qt < 4; ++qt) {
            ls[qt][0] = 0.f; ls[qt][1] = 0.f;
            #pragma unroll
            for (int nt = 0; nt < 4; ++nt)
                #pragma unroll
                for (int cc = 0; cc < 4; ++cc) O[qt][nt][cc] = 0.f;
        }
        #pragma unroll
        for (int st = 0; st < CHUNK/16; ++st) {
            unsigned Bk[2][2][2], Bv[4][2];
            unsigned ak = ak0 + (unsigned)(st*16*KPITCH*2);
            unsigned av = av0 + (unsigned)(st*16*KPITCH*2);
            ldsm4(Bk[0][0][0], Bk[0][0][1], Bk[1][0][0], Bk[1][0][1], ak);
            ldsm4(Bk[0][1][0], Bk[0][1][1], Bk[1][1][0], Bk[1][1][1], ak + 32);
            ldsm4t(Bv[0][0], Bv[0][1], Bv[1][0], Bv[1][1], av);
            ldsm4t(Bv[2][0], Bv[2][1], Bv[3][0], Bv[3][1], av + 32);
            #pragma unroll
            for (int qt = 0; qt < 4; ++qt) {
                float S0[4] = {0,0,0,0}, S1[4] = {0,0,0,0};
                mma16816(S0, Aq[qt][0], Bk[0][0]);
                mma16816(S1, Aq[qt][0], Bk[1][0]);
                mma16816(S0, Aq[qt][1], Bk[0][1]);
                mma16816(S1, Aq[qt][1], Bk[1][1]);
                float p0 = ex2(S0[0]), p1 = ex2(S0[1]), p2 = ex2(S0[2]), p3 = ex2(S0[3]);
                float p4 = ex2(S1[0]), p5 = ex2(S1[1]), p6 = ex2(S1[2]), p7 = ex2(S1[3]);
                ls[qt][0] += (p0 + p1) + (p4 + p5);
                ls[qt][1] += (p2 + p3) + (p6 + p7);
                unsigned P[4] = { pk(p0, p1), pk(p2, p3), pk(p4, p5), pk(p6, p7) };
                #pragma unroll
                for (int nt = 0; nt < 4; ++nt)
                    mma16816(O[qt][nt], P, Bv[nt]);
            }
        }
        #pragma unroll
        for (int qt = 0; qt < 4; ++qt) {
            float l0 = ls[qt][0], l1 = ls[qt][1];
            l0 += __shfl_xor_sync(0xffffffffu, l0, 1);
            l0 += __shfl_xor_sync(0xffffffffu, l0, 2);
            l1 += __shfl_xor_sync(0xffffffffu, l1, 1);
            l1 += __shfl_xor_sync(0xffffffffu, l1, 2);
            int n0 = qb0 + qt*16 + g;
            if (q == 0) {
                gPartL[(hh*NQ + n0)*NCH + ch]   = l0;
                gPartL[(hh*NQ + n0+8)*NCH + ch] = l1;
            }
            #pragma unroll
            for (int nt = 0; nt < 4; ++nt) {
                *(unsigned*)(gPartOB + ((size_t)(hh*NQ + n0)*NCH + ch)*32 + nt*8 + 2*q)
                    = pk(O[qt][nt][0], O[qt][nt][1]);
                *(unsigned*)(gPartOB + ((size_t)(hh*NQ + n0+8)*NCH + ch)*32 + nt*8 + 2*q)
                    = pk(O[qt][nt][2], O[qt][nt][3]);
            }
        }
    }
}

// ---------------- 5: merge stage 1 — sum partials per (h,n) -----------------
__global__ void __launch_bounds__(256) merge1_kernel() {
    __shared__ float sacc[8][33];
    __shared__ float sl[8];
    int hn = blockIdx.x;          // 0..1023 = h*NQ + n
    int t = threadIdx.x;          // 256
    int d = t & 31, cg = t >> 5;  // 8 chunk groups of 64
    const unsigned short* po = gPartOB + ((size_t)hn*NCH + cg*64)*32 + d;
    float a0 = 0.f, a1 = 0.f;
    #pragma unroll 8
    for (int c = 0; c < 64; c += 2) {
        a0 += __bfloat162float(*(const __nv_bfloat16*)(po + c*32));
        a1 += __bfloat162float(*(const __nv_bfloat16*)(po + (c+1)*32));
    }
    sacc[cg][d] = a0 + a1;
    const float* pl = gPartL + (size_t)hn*NCH;
    float l = pl[t] + pl[t+256];
    #pragma unroll
    for (int o = 16; o > 0; o >>= 1) l += __shfl_xor_sync(0xffffffffu, l, o);
    if (d == 0) sl[cg] = l;
    __syncthreads();
    if (t < 32) {
        float s = 0.f;
        #pragma unroll
        for (int gg = 0; gg < 8; ++gg) s += sacc[gg][t];
        gAccO[hn*32 + t] = s;
    } else if (t == 32) {
        float s = 0.f;
        #pragma unroll
        for (int gg = 0; gg < 8; ++gg) s += sl[gg];
        gAccL[hn] = s;
    }
}

// ---------------- 6: merge stage 2 — out-proj + residual + LayerNorm --------
__global__ void merge2_kernel(const float* __restrict__ x,
                              const float* __restrict__ out_w,
                              const float* __restrict__ ln_g,
                              const float* __restrict__ ln_b,
                              float* __restrict__ out) {
    __shared__ float o_s[128];
    __shared__ float r_s[256];
    __shared__ float red[4];
    int n = blockIdx.x;
    int t = threadIdx.x;    // 128
    int h = t >> 5, d = t & 31;
    o_s[h*32 + d] = gAccO[(h*NQ + n)*32 + d] / gAccL[h*NQ + n];
    __syncthreads();
    for (int k = 0; k < 2; ++k) {
        int dd = t + k*128;
        float a = x[n*256 + dd];
        const float4* wp = (const float4*)(out_w + dd*128);
        const float4* op = (const float4*)o_s;
        #pragma unroll 8
        for (int u = 0; u < 32; ++u) {
            float4 aa = wp[u]; float4 bb = op[u];
            a += aa.x*bb.x + aa.y*bb.y + aa.z*bb.z + aa.w*bb.w;
        }
        r_s[dd] = a;
    }
    __syncthreads();
    float s = r_s[t] + r_s[t+128];
    #pragma unroll
    for (int o = 16; o > 0; o >>= 1) s += __shfl_xor_sync(0xffffffffu, s, o);
    if ((t & 31) == 0) red[t >> 5] = s;
    __syncthreads();
    float mu = (red[0] + red[1] + red[2] + red[3]) * (1.f/256.f);
    float d0 = r_s[t] - mu, d1 = r_s[t+128] - mu;
    float sq = d0*d0 + d1*d1;
    #pragma unroll
    for (int o = 16; o > 0; o >>= 1) sq += __shfl_xor_sync(0xffffffffu, sq, o);
    __syncthreads();
    if ((t & 31) == 0) red[t >> 5] = sq;
    __syncthreads();
    float var = (red[0] + red[1] + red[2] + red[3]) * (1.f/256.f);
    float rstd = rsqrtf(var + 1e-5f);
    out[n*256 + t]       = d0*rstd*ln_g[t]     + ln_b[t];
    out[n*256 + t + 128] = d1*rstd*ln_g[t+128] + ln_b[t+128];
}

// ---------------- launcher --------------------------------------------------
extern "C" void kernel_launch(void* const* d_in, const int* in_sizes, int n_in,
                              void* d_out, int out_size) {
    const float* x       = (const float*)d_in[0];
    const float* y       = (const float*)d_in[1];
    const float* x_pos   = (const float*)d_in[2];
    const float* y_pos   = (const float*)d_in[3];
    const float* theta_w = (const float*)d_in[4];
    const float* phi_w   = (const float*)d_in[5];
    const float* g_w     = (const float*)d_in[6];
    const float* q_w1    = (const float*)d_in[7];
    const float* q_b1    = (const float*)d_in[8];
    const float* q_w2    = (const float*)d_in[9];
    const float* q_b2    = (const float*)d_in[10];
    const float* k_w1    = (const float*)d_in[11];
    const float* k_b1    = (const float*)d_in[12];
    const float* k_w2    = (const float*)d_in[13];
    const float* k_b2    = (const float*)d_in[14];
    const float* out_w   = (const float*)d_in[15];
    const float* ln_g    = (const float*)d_in[16];
    const float* ln_b    = (const float*)d_in[17];
    float* out = (float*)d_out;

    cudaFuncSetAttribute(projcd_kernel, cudaFuncAttributeMaxDynamicSharedMemorySize, PC_SMEM);
    cudaFuncSetAttribute(fused_kernel,  cudaFuncAttributeMaxDynamicSharedMemorySize, FZ_SMEM);

    projcd_kernel<<<64, 256, PC_SMEM>>>(x, y, phi_w, g_w, theta_w,
                                        k_w2, k_b2, q_w2, q_b2);
    q_kernel<<<256, 128>>>(x_pos, q_w1, q_b1);
    fused_kernel<<<512, 256, FZ_SMEM>>>(x_pos, y_pos, k_w1, k_b1);
    merge1_kernel<<<HH*NQ, 256>>>();
    merge2_kernel<<<NQ, 128>>>(x, out_w, ln_g, ln_b, out);
}

// round 12
// speedup vs baseline: 1.6492x; 1.6492x over previous
#include <cuda_runtime.h>
#include <cuda_bf16.h>
#include <math.h>

#define NQ 256
#define MM 256
#define EE 128
#define HH 4
#define PP 64
#define NK (NQ*MM)        // 65536 keys
#define CHUNK 256
#define NCH (NK/CHUNK)    // 256 chunks per head (= one np per chunk)

// ---------------- device scratch (static: no allocation allowed) ----------
__device__ float gPxT[NQ*EE];
__device__ float gPyT[MM*EE];
__device__ float gGxT[NQ*EE];
__device__ float gGyT[MM*EE];
__device__ float gQxT[NQ*EE];             // theta_x @ x^T
__device__ float gdphi[EE];
__device__ float gdg[EE];
__device__ float gdth[EE];
__device__ float gCthT[PP*EE];            // f32 [p][e]  (theta_e @ q_w2)^T
__device__ float gQ[HH*NQ*32];            // pre-scaled by 1/sqrt(32)*log2(e)
__device__ unsigned short gCphiB[EE*PP];  // bf16 [e][p]
__device__ unsigned short gCgB[EE*PP];    // bf16 [e][p]
__device__ unsigned short gPartOB[(size_t)HH*NQ*NCH*32];  // bf16, 16.8 MB
__device__ float gPartL[HH*NQ*NCH];       // 1 MB
__device__ float gAccO[HH*NQ*32];         // 128 KB
__device__ float gAccL[HH*NQ];

// ---------------- mma / ldmatrix helpers ------------------------------------
__device__ __forceinline__ unsigned pk(float lo, float hi) {
    unsigned d;
    asm("cvt.rn.bf16x2.f32 %0, %1, %2;" : "=r"(d) : "f"(hi), "f"(lo));
    return d;
}
__device__ __forceinline__ float ex2(float x) {
    float d;
    asm("ex2.approx.f32 %0, %1;" : "=f"(d) : "f"(x));
    return d;
}
__device__ __forceinline__ void mma16816(float* c, const unsigned* a, const unsigned* b) {
    asm volatile(
        "mma.sync.aligned.m16n8k16.row.col.f32.bf16.bf16.f32 "
        "{%0,%1,%2,%3},{%4,%5,%6,%7},{%8,%9},{%0,%1,%2,%3};"
        : "+f"(c[0]), "+f"(c[1]), "+f"(c[2]), "+f"(c[3])
        : "r"(a[0]), "r"(a[1]), "r"(a[2]), "r"(a[3]), "r"(b[0]), "r"(b[1]));
}
__device__ __forceinline__ void ldsm4(unsigned& x, unsigned& y, unsigned& z, unsigned& w,
                                      unsigned addr) {
    asm volatile("ldmatrix.sync.aligned.m8n8.x4.shared.b16 {%0,%1,%2,%3}, [%4];"
                 : "=r"(x), "=r"(y), "=r"(z), "=r"(w) : "r"(addr));
}
__device__ __forceinline__ void ldsm4t(unsigned& x, unsigned& y, unsigned& z, unsigned& w,
                                       unsigned addr) {
    asm volatile("ldmatrix.sync.aligned.m8n8.x4.trans.shared.b16 {%0,%1,%2,%3}, [%4];"
                 : "=r"(x), "=r"(y), "=r"(z), "=r"(w) : "r"(addr));
}

// ---------------- 1: proj (bf16 mma) + cd, one launch -----------------------
#define PJ_W_OFF 0
#define PJ_R_OFF 69632
#define WE_PITCH 129
#define PC_SMEM  98816
__global__ void __launch_bounds__(256) projcd_kernel(
        const float* __restrict__ x, const float* __restrict__ y,
        const float* __restrict__ phi_w, const float* __restrict__ g_w,
        const float* __restrict__ theta_w,
        const float* __restrict__ k_w2, const float* __restrict__ k_b2,
        const float* __restrict__ q_w2, const float* __restrict__ q_b2) {
    extern __shared__ char smc[];
    int tid = threadIdx.x;  // 256
    if (blockIdx.x < 40) {
        unsigned short* Wb = (unsigned short*)(smc + PJ_W_OFF);  // [128][264]
        unsigned short* Rb = (unsigned short*)(smc + PJ_R_OFF);  // [32][264]
        int combo = blockIdx.x >> 3;   // 0..4
        int rt    = blockIdx.x & 7;    // 32-row tile
        const float* w    = (combo < 2) ? phi_w : (combo < 4) ? g_w : theta_w;
        const float* srcp = (combo == 1 || combo == 3) ? y : x;
        float* outT = combo==0 ? gPxT : combo==1 ? gPyT : combo==2 ? gGxT
                    : combo==3 ? gGyT : gQxT;
        for (int idx = tid; idx < 128*128; idx += 256) {
            int e = idx >> 7, c = idx & 127;
            float2 f = *(const float2*)(w + e*384 + c*2);
            ((unsigned*)(Wb + e*264))[c] = pk(f.x, f.y);
        }
        for (int idx = tid; idx < 32*128; idx += 256) {
            int r = idx >> 7, c = idx & 127;
            float2 f = *(const float2*)(srcp + (rt*32 + r)*256 + c*2);
            ((unsigned*)(Rb + r*264))[c] = pk(f.x, f.y);
        }
        __syncthreads();
        int wq = tid >> 5, lane = tid & 31, g = lane >> 2, q = lane & 3;
        int mtile = wq & 1;
        int eg    = wq >> 1;
        int arow = mtile*16 + (lane & 7) + ((lane >> 3) & 1)*8;
        int acol = ((lane >> 4) & 1)*8;
        unsigned rbase = (unsigned)__cvta_generic_to_shared(Rb);
        unsigned wbase = (unsigned)__cvta_generic_to_shared(Wb)
                       + (unsigned)(((eg*32 + (lane & 7))*264 + (lane >> 3)*8)*2);
        float C[4][4];
        #pragma unroll
        for (int ng = 0; ng < 4; ++ng)
            #pragma unroll
            for (int i = 0; i < 4; ++i) C[ng][i] = 0.f;
        #pragma unroll
        for (int kb = 0; kb < 8; ++kb) {
            unsigned A0[4], A1[4];
            unsigned abase = rbase + (unsigned)((arow*264 + kb*32 + acol)*2);
            ldsm4(A0[0], A0[1], A0[2], A0[3], abase);
            ldsm4(A1[0], A1[1], A1[2], A1[3], abase + 32);
            #pragma unroll
            for (int ng = 0; ng < 4; ++ng) {
                unsigned b[4];
                ldsm4(b[0], b[1], b[2], b[3], wbase + (unsigned)((ng*8*264 + kb*32)*2));
                mma16816(C[ng], A0, b);
                mma16816(C[ng], A1, b + 2);
            }
        }
        int row = rt*32 + mtile*16 + g;
        #pragma unroll
        for (int ng = 0; ng < 4; ++ng) {
            int e = eg*32 + ng*8 + 2*q;
            float2 v0; v0.x = C[ng][0]; v0.y = C[ng][1];
            float2 v1; v1.x = C[ng][2]; v1.y = C[ng][3];
            *(float2*)(outT + row*128 + e)     = v0;
            *(float2*)(outT + (row+8)*128 + e) = v1;
        }
    } else {
        float* we  = (float*)smc;              // 128 x 129
        float* kw2 = (float*)(smc + 66048);    // 128 x 64
        int bid2 = blockIdx.x - 40;
        int wi = bid2 % 3;
        int pg = bid2 / 3;
        const float* w   = wi==0 ? phi_w : wi==1 ? g_w : theta_w;
        const float* w2  = wi==2 ? q_w2 : k_w2;
        const float* b2  = wi==2 ? q_b2 : k_b2;
        unsigned short* CtB = wi==1 ? gCgB : gCphiB;
        float* dv  = wi==0 ? gdphi : wi==1 ? gdg : gdth;
        for (int idx = tid; idx < 128*128; idx += 256) {
            int e = idx >> 7, c = idx & 127;
            we[e*WE_PITCH + c] = w[e*384 + 256 + c];
        }
        for (int idx = tid; idx < 128*64; idx += 256) kw2[idx] = w2[idx];
        __syncthreads();
        int e  = tid & 127;
        int ph = tid >> 7;
        if (pg == 0 && ph == 0) {
            float acc = 0.f;
            for (int c = 0; c < 128; ++c) acc += we[e*WE_PITCH + c]*b2[c];
            dv[e] = acc;
        }
        for (int j = 0; j < 4; ++j) {
            int p = pg*8 + ph*4 + j;
            float acc = 0.f;
            #pragma unroll 8
            for (int c = 0; c < 128; ++c)
                acc += we[e*WE_PITCH + c] * kw2[c*64 + p];
            if (wi == 2) {
                gCthT[p*128 + e] = acc;
            } else {
                __nv_bfloat16 b = __float2bfloat16(acc);
                CtB[e*64 + p] = *(unsigned short*)&b;
            }
        }
    }
}

// ---------------- 3: Q = scale * (Qx + Cth^T hid + dth) ---------------------
__global__ void q_kernel(const float* __restrict__ x_pos,
                         const float* __restrict__ q_w1,
                         const float* __restrict__ q_b1) {
    __shared__ float hid[64];
    int n = blockIdx.x;
    int t = threadIdx.x;   // 128
    if (t < 64) {
        float r0 = x_pos[n*3], r1 = x_pos[n*3+1], r2 = x_pos[n*3+2];
        float h = q_w1[t*3]*r0 + q_w1[t*3+1]*r1 + q_w1[t*3+2]*r2 + q_b1[t];
        hid[t] = fmaxf(h, 0.f);
    }
    __syncthreads();
    int e = t;
    float a0 = 0.f, a1 = 0.f;
    #pragma unroll
    for (int p = 0; p < 64; p += 2) {
        a0 += gCthT[p*128 + e]     * hid[p];
        a1 += gCthT[(p+1)*128 + e] * hid[p+1];
    }
    float acc = gQxT[n*128 + e] + a0 + a1 + gdth[e];
    acc *= 0.17677669529663687f * 1.4426950408889634f;
    int h = e >> 5, d = e & 31;
    gQ[(h*NQ + n)*32 + d] = acc;
}

// ---------------- 4: FUSED genkv + flash attention (R8 structure) -----------
#define KPITCH 136
#define FZ_KS_OFF 0
#define FZ_VS_OFF 69632
#define FZ_H_OFF  139264
#define FZ_CP_OFF 176128
#define FZ_CG_OFF 194560
#define FZ_BK_OFF 212992
#define FZ_BV_OFF 213504
#define FZ_YP_OFF 214016
#define FZ_SMEM   217088

__global__ void __launch_bounds__(512, 1) fused_kernel(
        const float* __restrict__ x_pos, const float* __restrict__ y_pos,
        const float* __restrict__ k_w1, const float* __restrict__ k_b1) {
    extern __shared__ char smc[];
    unsigned short* Ks = (unsigned short*)(smc + FZ_KS_OFF);  // [256][136] bf16
    unsigned short* Vs = (unsigned short*)(smc + FZ_VS_OFF);  // [256][136] bf16
    unsigned short* Hs = (unsigned short*)(smc + FZ_H_OFF);   // [256][72]  bf16
    float* baseK = (float*)(smc + FZ_BK_OFF);
    float* baseV = (float*)(smc + FZ_BV_OFF);
    float* yps   = (float*)(smc + FZ_YP_OFF);                 // [256][3]
    __shared__ float kw1s[192], kb1s[64];
    int tid = threadIdx.x;   // 512
    int np  = blockIdx.x;    // 0..255  (chunk index, NCH=256)

    // ---- phase A: stage constants + hidden MLP ----
    for (int i = tid; i < 128*32; i += 512) {
        int e = i >> 5, c = i & 31;
        ((unsigned*)(smc + FZ_CP_OFF + e*144))[c] = ((const unsigned*)gCphiB)[e*32 + c];
        ((unsigned*)(smc + FZ_CG_OFF + e*144))[c] = ((const unsigned*)gCgB)[e*32 + c];
    }
    if (tid < 128) {
        baseK[tid] = gPxT[np*128 + tid] + gdphi[tid];
        baseV[tid] = gGxT[np*128 + tid] + gdg[tid];
    }
    for (int i = tid; i < 768; i += 512) yps[i] = y_pos[i];
    if (tid < 192) kw1s[tid] = k_w1[tid];
    if (tid >= 256 && tid < 320) kb1s[tid-256] = k_b1[tid-256];
    __syncthreads();
    float xp0 = x_pos[np*3], xp1 = x_pos[np*3+1], xp2 = x_pos[np*3+2];
    for (int i = tid; i < 256*64; i += 512) {
        int pr = i >> 6, p = i & 63;
        float r0 = xp0 - yps[pr*3], r1 = xp1 - yps[pr*3+1], r2 = xp2 - yps[pr*3+2];
        float h = fmaxf(kw1s[p*3]*r0 + kw1s[p*3+1]*r1 + kw1s[p*3+2]*r2 + kb1s[p], 0.f);
        __nv_bfloat16 hb = __float2bfloat16(h);
        Hs[pr*72 + p] = *(unsigned short*)&hb;
    }
    __syncthreads();

    int w = tid >> 5, lane = tid & 31, g = lane >> 2, q = lane & 3;

    // ---- phase B: K/V = H@C + base - Py/Gy  -> SMEM (16 warps x 16 rows) ----
    {
        int r0 = w*16;
        unsigned A[4][4];
        int arow = r0 + (lane & 7) + ((lane >> 3) & 1)*8;
        int acol = ((lane >> 4) & 1)*8;
        unsigned hbase = (unsigned)__cvta_generic_to_shared(Hs);
        #pragma unroll
        for (int kt = 0; kt < 4; ++kt)
            ldsm4(A[kt][0], A[kt][1], A[kt][2], A[kt][3],
                  hbase + (unsigned)((arow*72 + kt*16 + acol)*2));
        unsigned cpb = (unsigned)__cvta_generic_to_shared(smc + FZ_CP_OFF);
        unsigned cgb = (unsigned)__cvta_generic_to_shared(smc + FZ_CG_OFF);
        int brow = lane & 7;
        int bcol = (lane >> 3)*8;
        int m  = r0 + g;
        int m2 = m + 8;
        // prefetch Py/Gy for nt=0
        float2 pK0 = *(const float2*)(gPyT + m*128  + 2*q);
        float2 pK1 = *(const float2*)(gPyT + m2*128 + 2*q);
        float2 pV0 = *(const float2*)(gGyT + m*128  + 2*q);
        float2 pV1 = *(const float2*)(gGyT + m2*128 + 2*q);
        #pragma unroll
        for (int nt = 0; nt < 16; ++nt) {
            unsigned off1 = (unsigned)(((nt*8 + brow)*72 + bcol)*2);
            unsigned bP[4][2], bG[4][2];
            ldsm4(bP[0][0], bP[0][1], bP[1][0], bP[1][1], cpb + off1);
            ldsm4(bP[2][0], bP[2][1], bP[3][0], bP[3][1], cpb + off1 + 64);
            ldsm4(bG[0][0], bG[0][1], bG[1][0], bG[1][1], cgb + off1);
            ldsm4(bG[2][0], bG[2][1], bG[3][0], bG[3][1], cgb + off1 + 64);
            float cK[4] = {0.f,0.f,0.f,0.f}, cV[4] = {0.f,0.f,0.f,0.f};
            #pragma unroll
            for (int kt = 0; kt < 4; ++kt) {
                mma16816(cK, A[kt], bP[kt]);
                mma16816(cV, A[kt], bG[kt]);
            }
            int e0 = nt*8 + 2*q;
            float2 cuK0 = pK0, cuK1 = pK1, cuV0 = pV0, cuV1 = pV1;
            if (nt < 15) {
                int e1 = e0 + 8;
                pK0 = *(const float2*)(gPyT + m*128  + e1);
                pK1 = *(const float2*)(gPyT + m2*128 + e1);
                pV0 = *(const float2*)(gGyT + m*128  + e1);
                pV1 = *(const float2*)(gGyT + m2*128 + e1);
            }
            float2 bk = *(const float2*)(baseK + e0);
            float2 bv = *(const float2*)(baseV + e0);
            *(unsigned*)(Ks + m *KPITCH + e0) = pk(cK[0]+bk.x-cuK0.x, cK[1]+bk.y-cuK0.y);
            *(unsigned*)(Ks + m2*KPITCH + e0) = pk(cK[2]+bk.x-cuK1.x, cK[3]+bk.y-cuK1.y);
            *(unsigned*)(Vs + m *KPITCH + e0) = pk(cV[0]+bv.x-cuV0.x, cV[1]+bv.y-cuV0.y);
            *(unsigned*)(Vs + m2*KPITCH + e0) = pk(cV[2]+bv.x-cuV1.x, cV[3]+bv.y-cuV1.y);
        }
    }
    __syncthreads();

    // ---- phase C: attention, 32 units = (head, 32-query tile); 2 per warp ----
    unsigned ksb = (unsigned)__cvta_generic_to_shared(Ks);
    unsigned vsb = (unsigned)__cvta_generic_to_shared(Vs);
    int kRow = (lane & 7) + ((lane >> 4) & 1)*8;
    int kCol = ((lane >> 3) & 1)*8;
    int vRow = (lane & 7) + ((lane >> 3) & 1)*8;
    int vCol = ((lane >> 4) & 1)*8;
    for (int u = 0; u < 2; ++u) {
        int unit = w + u*16;          // 0..31
        int hh = unit >> 3;           // head
        int qb = (unit & 7)*32;       // query tile base
        unsigned Aq[2][2][4];
        const float* Qp = gQ + hh*NQ*32;
        #pragma unroll
        for (int mt = 0; mt < 2; ++mt)
          #pragma unroll
          for (int kt = 0; kt < 2; ++kt) {
            int rA = qb + mt*16 + g, rB = rA + 8;
            int c0 = kt*16 + 2*q, c1 = c0 + 8;
            float2 f;
            f = *(const float2*)(Qp + rA*32 + c0); Aq[mt][kt][0] = pk(f.x, f.y);
            f = *(const float2*)(Qp + rB*32 + c0); Aq[mt][kt][1] = pk(f.x, f.y);
            f = *(const float2*)(Qp + rA*32 + c1); Aq[mt][kt][2] = pk(f.x, f.y);
            f = *(const float2*)(Qp + rB*32 + c1); Aq[mt][kt][3] = pk(f.x, f.y);
          }
        float O[2][4][4];
        #pragma unroll
        for (int a = 0; a < 2; ++a)
            #pragma unroll
            for (int b = 0; b < 4; ++b)
                #pragma unroll
                for (int cc = 0; cc < 4; ++cc) O[a][b][cc] = 0.f;
        float ls[2][2] = {{0.f, 0.f}, {0.f, 0.f}};
        #pragma unroll
        for (int st = 0; st < CHUNK/16; ++st) {
            int key0 = st*16;
            unsigned Bk[2][2][2];  // [ntk][kt][reg]
            unsigned ak = ksb + (unsigned)(((key0 + kRow)*KPITCH + hh*32 + kCol)*2);
            ldsm4(Bk[0][0][0], Bk[0][0][1], Bk[1][0][0], Bk[1][0][1], ak);
            ldsm4(Bk[0][1][0], Bk[0][1][1], Bk[1][1][0], Bk[1][1][1], ak + 32);
            unsigned Bv[4][2];
            unsigned av = vsb + (unsigned)(((key0 + vRow)*KPITCH + hh*32 + vCol)*2);
            ldsm4t(Bv[0][0], Bv[0][1], Bv[1][0], Bv[1][1], av);
            ldsm4t(Bv[2][0], Bv[2][1], Bv[3][0], Bv[3][1], av + 32);
            #pragma unroll
            for (int mt = 0; mt < 2; ++mt) {
                float S0[4] = {0,0,0,0}, S1[4] = {0,0,0,0};
                mma16816(S0, Aq[mt][0], Bk[0][0]);
                mma16816(S1, Aq[mt][0], Bk[1][0]);
                mma16816(S0, Aq[mt][1], Bk[0][1]);
                mma16816(S1, Aq[mt][1], Bk[1][1]);
                float p0 = ex2(S0[0]), p1 = ex2(S0[1]), p2 = ex2(S0[2]), p3 = ex2(S0[3]);
                float p4 = ex2(S1[0]), p5 = ex2(S1[1]), p6 = ex2(S1[2]), p7 = ex2(S1[3]);
                ls[mt][0] += (p0 + p1) + (p4 + p5);
                ls[mt][1] += (p2 + p3) + (p6 + p7);
                unsigned P[4] = { pk(p0, p1), pk(p2, p3), pk(p4, p5), pk(p6, p7) };
                #pragma unroll
                for (int nt = 0; nt < 4; ++nt)
                    mma16816(O[mt][nt], P, Bv[nt]);
            }
        }
        #pragma unroll
        for (int mt = 0; mt < 2; ++mt) {
            float l0 = ls[mt][0], l1 = ls[mt][1];
            l0 += __shfl_xor_sync(0xffffffffu, l0, 1);
            l0 += __shfl_xor_sync(0xffffffffu, l0, 2);
            l1 += __shfl_xor_sync(0xffffffffu, l1, 1);
            l1 += __shfl_xor_sync(0xffffffffu, l1, 2);
            int n0 = qb + mt*16 + g;
            if (q == 0) {
                gPartL[(hh*NQ + n0)*NCH + np]   = l0;
                gPartL[(hh*NQ + n0+8)*NCH + np] = l1;
            }
            #pragma unroll
            for (int nt = 0; nt < 4; ++nt) {
                *(unsigned*)(gPartOB + ((size_t)(hh*NQ + n0)*NCH + np)*32 + nt*8 + 2*q)
                    = pk(O[mt][nt][0], O[mt][nt][1]);
                *(unsigned*)(gPartOB + ((size_t)(hh*NQ + n0+8)*NCH + np)*32 + nt*8 + 2*q)
                    = pk(O[mt][nt][2], O[mt][nt][3]);
            }
        }
    }
}

// ---------------- 5: merge stage 1 — sum partials per (h,n) -----------------
__global__ void __launch_bounds__(256) merge1_kernel() {
    __shared__ float sacc[8][33];
    __shared__ float sl[8];
    int hn = blockIdx.x;          // 0..1023 = h*NQ + n
    int t = threadIdx.x;          // 256
    int d = t & 31, cg = t >> 5;  // 8 chunk groups of 32
    const unsigned short* po = gPartOB + ((size_t)hn*NCH + cg*32)*32 + d;
    float a0 = 0.f, a1 = 0.f;
    #pragma unroll 8
    for (int c = 0; c < 32; c += 2) {
        a0 += __bfloat162float(*(const __nv_bfloat16*)(po + c*32));
        a1 += __bfloat162float(*(const __nv_bfloat16*)(po + (c+1)*32));
    }
    sacc[cg][d] = a0 + a1;
    float l = gPartL[(size_t)hn*NCH + cg*32 + d];
    #pragma unroll
    for (int o = 16; o > 0; o >>= 1) l += __shfl_xor_sync(0xffffffffu, l, o);
    if (d == 0) sl[cg] = l;
    __syncthreads();
    if (t < 32) {
        float s = 0.f;
        #pragma unroll
        for (int gg = 0; gg < 8; ++gg) s += sacc[gg][t];
        gAccO[hn*32 + t] = s;
    } else if (t == 32) {
        float s = 0.f;
        #pragma unroll
        for (int gg = 0; gg < 8; ++gg) s += sl[gg];
        gAccL[hn] = s;
    }
}

// ---------------- 6: merge stage 2 — out-proj + residual + LayerNorm --------
__global__ void merge2_kernel(const float* __restrict__ x,
                              const float* __restrict__ out_w,
                              const float* __restrict__ ln_g,
                              const float* __restrict__ ln_b,
                              float* __restrict__ out) {
    __shared__ float o_s[128];
    __shared__ float r_s[256];
    __shared__ float red[4];
    int n = blockIdx.x;
    int t = threadIdx.x;    // 128
    int h = t >> 5, d = t & 31;
    o_s[h*32 + d] = gAccO[(h*NQ + n)*32 + d] / gAccL[h*NQ + n];
    __syncthreads();
    for (int k = 0; k < 2; ++k) {
        int dd = t + k*128;
        float a = x[n*256 + dd];
        const float4* wp = (const float4*)(out_w + dd*128);
        const float4* op = (const float4*)o_s;
        #pragma unroll 8
        for (int u = 0; u < 32; ++u) {
            float4 aa = wp[u]; float4 bb = op[u];
            a += aa.x*bb.x + aa.y*bb.y + aa.z*bb.z + aa.w*bb.w;
        }
        r_s[dd] = a;
    }
    __syncthreads();
    float s = r_s[t] + r_s[t+128];
    #pragma unroll
    for (int o = 16; o > 0; o >>= 1) s += __shfl_xor_sync(0xffffffffu, s, o);
    if ((t & 31) == 0) red[t >> 5] = s;
    __syncthreads();
    float mu = (red[0] + red[1] + red[2] + red[3]) * (1.f/256.f);
    float d0 = r_s[t] - mu, d1 = r_s[t+128] - mu;
    float sq = d0*d0 + d1*d1;
    #pragma unroll
    for (int o = 16; o > 0; o >>= 1) sq += __shfl_xor_sync(0xffffffffu, sq, o);
    __syncthreads();
    if ((t & 31) == 0) red[t >> 5] = sq;
    __syncthreads();
    float var = (red[0] + red[1] + red[2] + red[3]) * (1.f/256.f);
    float rstd = rsqrtf(var + 1e-5f);
    out[n*256 + t]       = d0*rstd*ln_g[t]     + ln_b[t];
    out[n*256 + t + 128] = d1*rstd*ln_g[t+128] + ln_b[t+128];
}

// ---------------- launcher --------------------------------------------------
extern "C" void kernel_launch(void* const* d_in, const int* in_sizes, int n_in,
                              void* d_out, int out_size) {
    const float* x       = (const float*)d_in[0];
    const float* y       = (const float*)d_in[1];
    const float* x_pos   = (const float*)d_in[2];
    const float* y_pos   = (const float*)d_in[3];
    const float* theta_w = (const float*)d_in[4];
    const float* phi_w   = (const float*)d_in[5];
    const float* g_w     = (const float*)d_in[6];
    const float* q_w1    = (const float*)d_in[7];
    const float* q_b1    = (const float*)d_in[8];
    const float* q_w2    = (const float*)d_in[9];
    const float* q_b2    = (const float*)d_in[10];
    const float* k_w1    = (const float*)d_in[11];
    const float* k_b1    = (const float*)d_in[12];
    const float* k_w2    = (const float*)d_in[13];
    const float* k_b2    = (const float*)d_in[14];
    const float* out_w   = (const float*)d_in[15];
    const float* ln_g    = (const float*)d_in[16];
    const float* ln_b    = (const float*)d_in[17];
    float* out = (float*)d_out;

    cudaFuncSetAttribute(projcd_kernel, cudaFuncAttributeMaxDynamicSharedMemorySize, PC_SMEM);
    cudaFuncSetAttribute(fused_kernel,  cudaFuncAttributeMaxDynamicSharedMemorySize, FZ_SMEM);

    projcd_kernel<<<64, 256, PC_SMEM>>>(x, y, phi_w, g_w, theta_w,
                                        k_w2, k_b2, q_w2, q_b2);
    q_kernel<<<256, 128>>>(x_pos, q_w1, q_b1);
    fused_kernel<<<256, 512, FZ_SMEM>>>(x_pos, y_pos, k_w1, k_b1);
    merge1_kernel<<<HH*NQ, 256>>>();
    merge2_kernel<<<NQ, 128>>>(x, out_w, ln_g, ln_b, out);
}